// round 16
// baseline (speedup 1.0000x reference)
#include <cuda_runtime.h>
#include <cuda_bf16.h>
#include <math.h>
#include <stdint.h>

// ---------------- problem dims ----------------
#define S_TOK   8192
#define HDIM    1024
#define EXP     8
#define IDIM    4096
#define CAP     2048

// ---------------- scratch (device globals) ----------------
__device__ __nv_bfloat16 g_lnb[(size_t)S_TOK * HDIM];        // 16 MB LN'ed tokens (bf16)
__device__ __nv_bfloat16 g_hb [(size_t)S_TOK * IDIM];        // 64 MB GEMM1 output (bf16)
__device__ __nv_bfloat16 g_wib[(size_t)EXP * IDIM * HDIM];   // 64 MB wi transposed: [e][n=IDIM][k=HDIM]
__device__ __nv_bfloat16 g_wob[(size_t)EXP * HDIM * IDIM];   // 64 MB wo transposed: [e][n=HDIM][k=IDIM]
__device__ int   g_top1[S_TOK];
__device__ float g_w[S_TOK];
__device__ int   g_perm[S_TOK];
__device__ int   g_off[EXP + 1];
__device__ int   g_work;                 // global work-queue cursor
__device__ int   g_strip[EXP * 16];      // per (expert, m-block) GEMM1 completion
__device__ int   g_wiT[EXP];             // per-expert wi transpose completion (->64)
__device__ int   g_woT[EXP];             // per-expert wo transpose completion (->64)

__device__ __forceinline__ uint32_t smem_u32(const void* p) {
    return (uint32_t)__cvta_generic_to_shared(p);
}

// =====================================================================
// K1: LayerNorm + residual copy + gating (fp32 exact) ; LN stored bf16
// =====================================================================
__global__ void __launch_bounds__(256) ln_gate_kernel(
    const float4* __restrict__ in4,
    const float4* __restrict__ gw4,
    const float4* __restrict__ gamma4,
    const float4* __restrict__ beta4,
    float4* __restrict__ out4)
{
    const int s   = blockIdx.x;
    const int tid = threadIdx.x;
    const int lane = tid & 31, wid = tid >> 5;

    float4 x = in4[(size_t)s * 256 + tid];

    float lsum = x.x + x.y + x.z + x.w;
    float lsq  = x.x * x.x + x.y * x.y + x.z * x.z + x.w * x.w;
    #pragma unroll
    for (int off = 16; off > 0; off >>= 1) {
        lsum += __shfl_down_sync(0xffffffffu, lsum, off);
        lsq  += __shfl_down_sync(0xffffffffu, lsq,  off);
    }
    __shared__ float s_a[8], s_b[8];
    if (lane == 0) { s_a[wid] = lsum; s_b[wid] = lsq; }
    __syncthreads();
    __shared__ float s_mean, s_rstd;
    if (tid == 0) {
        float a = 0.f, b = 0.f;
        #pragma unroll
        for (int w = 0; w < 8; w++) { a += s_a[w]; b += s_b[w]; }
        float mean = a * (1.0f / HDIM);
        float var  = b * (1.0f / HDIM) - mean * mean;
        s_mean = mean;
        s_rstd = rsqrtf(var + 1e-5f);
    }
    __syncthreads();
    const float mean = s_mean, rstd = s_rstd;

    float4 g = gamma4[tid], bb = beta4[tid];
    float4 nrm;
    nrm.x = (x.x - mean) * rstd * g.x + bb.x;
    nrm.y = (x.y - mean) * rstd * g.y + bb.y;
    nrm.z = (x.z - mean) * rstd * g.z + bb.z;
    nrm.w = (x.w - mean) * rstd * g.w + bb.w;

    __nv_bfloat162 p0 = __floats2bfloat162_rn(nrm.x, nrm.y);
    __nv_bfloat162 p1 = __floats2bfloat162_rn(nrm.z, nrm.w);
    uint32_t* lnb32 = reinterpret_cast<uint32_t*>(g_lnb);
    lnb32[(size_t)s * 512 + tid * 2 + 0] = *reinterpret_cast<uint32_t*>(&p0);
    lnb32[(size_t)s * 512 + tid * 2 + 1] = *reinterpret_cast<uint32_t*>(&p1);

    out4[(size_t)s * 256 + tid] = x;   // residual pre-fill (covers dropped tokens)

    float p[EXP];
    #pragma unroll
    for (int e = 0; e < EXP; e++) {
        float4 w = gw4[(size_t)e * 256 + tid];
        p[e] = nrm.x * w.x + nrm.y * w.y + nrm.z * w.z + nrm.w * w.w;
    }
    #pragma unroll
    for (int e = 0; e < EXP; e++) {
        #pragma unroll
        for (int off = 16; off > 0; off >>= 1)
            p[e] += __shfl_down_sync(0xffffffffu, p[e], off);
    }
    __shared__ float s_l[EXP][8];
    if (lane == 0) {
        #pragma unroll
        for (int e = 0; e < EXP; e++) s_l[e][wid] = p[e];
    }
    __syncthreads();
    if (tid == 0) {
        float logit[EXP];
        #pragma unroll
        for (int e = 0; e < EXP; e++) {
            float v = 0.f;
            #pragma unroll
            for (int w = 0; w < 8; w++) v += s_l[e][w];
            logit[e] = v;
        }
        int best = 0; float bv = logit[0];
        #pragma unroll
        for (int e = 1; e < EXP; e++) if (logit[e] > bv) { bv = logit[e]; best = e; }
        float den = 0.f;
        #pragma unroll
        for (int e = 0; e < EXP; e++) den += expf(logit[e] - bv);
        g_top1[s] = best;
        g_w[s]    = 1.0f / den;
    }
}

// =====================================================================
// K2: exact token-order exclusive cumsum per expert + capacity drop.
// Also resets work-queue / gate counters for the fused kernel.
// =====================================================================
__device__ __forceinline__ uint4 u4add(uint4 a, uint4 b) {
    return make_uint4(a.x + b.x, a.y + b.y, a.z + b.z, a.w + b.w);
}

__global__ void __launch_bounds__(1024) scan_kernel()
{
    __shared__ uint4 s_wt[32];
    __shared__ int   s_koff[EXP + 1];

    const int tid = threadIdx.x;
    const int lane = tid & 31, wid = tid >> 5;

    // reset fused-kernel bookkeeping (every launch; graph replays)
    if (tid < EXP * 16) g_strip[tid] = 0;
    else if (tid < EXP * 16 + EXP)      g_wiT[tid - EXP * 16] = 0;
    else if (tid < EXP * 16 + 2 * EXP)  g_woT[tid - EXP * 16 - EXP] = 0;
    else if (tid == EXP * 16 + 2 * EXP) g_work = 0;

    int t[8];
    uint4 cnt = make_uint4(0, 0, 0, 0);
    uint32_t* cw = reinterpret_cast<uint32_t*>(&cnt);
    #pragma unroll
    for (int j = 0; j < 8; j++) {
        t[j] = g_top1[tid * 8 + j];
        cw[t[j] >> 1] += 1u << ((t[j] & 1) * 16);
    }

    uint4 incl = cnt;
    uint32_t* iw = reinterpret_cast<uint32_t*>(&incl);
    #pragma unroll
    for (int off = 1; off < 32; off <<= 1) {
        uint4 up;
        uint32_t* uw = reinterpret_cast<uint32_t*>(&up);
        #pragma unroll
        for (int c = 0; c < 4; c++) uw[c] = __shfl_up_sync(0xffffffffu, iw[c], off);
        if (lane >= off) incl = u4add(incl, up);
    }
    if (lane == 31) s_wt[wid] = incl;
    __syncthreads();

    if (wid == 0) {
        uint4 v = s_wt[lane];
        uint32_t* vw = reinterpret_cast<uint32_t*>(&v);
        #pragma unroll
        for (int off = 1; off < 32; off <<= 1) {
            uint4 up;
            uint32_t* uw = reinterpret_cast<uint32_t*>(&up);
            #pragma unroll
            for (int c = 0; c < 4; c++) uw[c] = __shfl_up_sync(0xffffffffu, vw[c], off);
            if (lane >= off) v = u4add(v, up);
        }
        s_wt[lane] = v;
        if (lane == 31) {
            int o = 0;
            #pragma unroll
            for (int e = 0; e < EXP; e++) {
                int tot = (vw[e >> 1] >> ((e & 1) * 16)) & 0xffff;
                s_koff[e] = o;
                o += min(tot, CAP);
            }
            s_koff[EXP] = o;
            #pragma unroll
            for (int i = 0; i <= EXP; i++) g_off[i] = s_koff[i];
        }
    }
    __syncthreads();

    uint4 base = (wid > 0) ? s_wt[wid - 1] : make_uint4(0, 0, 0, 0);
    int excl[EXP];
    uint32_t* bw = reinterpret_cast<uint32_t*>(&base);
    #pragma unroll
    for (int e = 0; e < EXP; e++) {
        int sh = (e & 1) * 16;
        excl[e] = (int)(((bw[e >> 1] >> sh) & 0xffff)
                      + ((iw[e >> 1] >> sh) & 0xffff)
                      - ((cw[e >> 1] >> sh) & 0xffff));
    }
    #pragma unroll
    for (int j = 0; j < 8; j++) {
        int e = t[j];
        int r = excl[e]++;
        int s = tid * 8 + j;
        if (r < CAP) g_perm[s_koff[e] + r] = s;
        else         g_w[s] = 0.0f;
    }
}

// =====================================================================
// Fused persistent kernel: weight transposes + both GEMMs, one work queue.
//   ids 0..63                      : wi-T e=0
//   per expert block e=0..7       : [wi-T e+1 (64, e<7)][wo-T e (64)][G1 e (512)]
//   tail                           : G2 (1024)
// Gates (all queue-order safe):
//   G1(e)  : g_wiT[e]==64
//   G2(e,m): g_strip[e*16+m]==32 && g_woT[e]==64
// =====================================================================
#define BM 128
#define BN 128
#define BK 32
#define LDK 40
#define STAGES 3
#define N_ITEMS 6144

__global__ void __launch_bounds__(256, 2) moe_fused(
    const float* __restrict__ inp, float* __restrict__ out,
    const float* __restrict__ wi, const float* __restrict__ wo)
{
    __shared__ __align__(16) __nv_bfloat16 As[STAGES][BM * LDK];
    __shared__ __nv_bfloat16 Bs[STAGES][BN * LDK];
    __shared__ int sRow[BM];
    __shared__ int s_item;

    const int tid = threadIdx.x;
    const int warp = tid >> 5, lane = tid & 31;
    const int wm = (warp >> 2) * 64;
    const int wn = (warp & 3) * 32;
    const int lr = tid >> 2;
    const int lkg = tid & 3;

    float* tileF = reinterpret_cast<float*>(&As[0][0]);   // 64x65 fp32 overlay

    for (;;) {
        __syncthreads();                         // protect s_item + smem reuse
        if (tid == 0) s_item = atomicAdd(&g_work, 1);
        __syncthreads();
        const int id = s_item;
        if (id >= N_ITEMS) break;

        // ---- decode work item ----
        int kind, e, sub;                        // 0 wiT, 1 woT, 2 G1, 3 G2
        if (id < 64) { kind = 0; e = 0; sub = id; }
        else if (id < 5120) {
            const int t  = id - 64;
            const int b  = t / 640;              // block 7 is short (576) but maps right
            const int o  = t - b * 640;
            if (b < 7) {
                if (o < 64)       { kind = 0; e = b + 1; sub = o; }
                else if (o < 128) { kind = 1; e = b;     sub = o - 64; }
                else              { kind = 2; e = b;     sub = o - 128; }
            } else {
                if (o < 64)       { kind = 1; e = 7; sub = o; }
                else              { kind = 2; e = 7; sub = o - 64; }
            }
        } else { kind = 3; const int t = id - 5120; e = t >> 7; sub = t & 127; }

        // =========== transpose items ===========
        if (kind <= 1) {
            const float* src;
            __nv_bfloat16* dst;
            int Csrc, Rdst, c0, rbase;
            if (kind == 0) {        // wi [1024][4096] -> wib [4096][1024]
                src = wi + (size_t)e * HDIM * IDIM;
                dst = g_wib + (size_t)e * (size_t)IDIM * HDIM;
                Csrc = IDIM; Rdst = HDIM;
                c0 = sub * 64; rbase = 0;
            } else {                // wo [4096][1024] -> wob [1024][4096]
                src = wo + (size_t)e * IDIM * HDIM;
                dst = g_wob + (size_t)e * (size_t)HDIM * IDIM;
                Csrc = HDIM; Rdst = IDIM;
                c0 = (sub & 15) * 64; rbase = (sub >> 4) * 1024;
            }
            for (int it = 0; it < 16; it++) {
                const int r0 = rbase + it * 64;
                {
                    const int r  = tid >> 2;
                    const int cg = (tid & 3) * 4;
                    const float* srow = src + (size_t)(r0 + r) * Csrc + c0;
                    #pragma unroll
                    for (int i = 0; i < 4; i++) {
                        float4 v = *reinterpret_cast<const float4*>(srow + (cg + i) * 4);
                        tileF[r * 65 + (cg + i) * 4 + 0] = v.x;
                        tileF[r * 65 + (cg + i) * 4 + 1] = v.y;
                        tileF[r * 65 + (cg + i) * 4 + 2] = v.z;
                        tileF[r * 65 + (cg + i) * 4 + 3] = v.w;
                    }
                }
                __syncthreads();
                #pragma unroll
                for (int p = 0; p < 2; p++) {
                    const int dr = p * 32 + (tid >> 3);
                    const int ch = tid & 7;
                    uint32_t pk[4];
                    #pragma unroll
                    for (int j = 0; j < 4; j++) {
                        __nv_bfloat162 b2 = __floats2bfloat162_rn(
                            tileF[(ch * 8 + 2 * j) * 65 + dr],
                            tileF[(ch * 8 + 2 * j + 1) * 65 + dr]);
                        pk[j] = *reinterpret_cast<uint32_t*>(&b2);
                    }
                    *reinterpret_cast<uint4*>(&dst[(size_t)(c0 + dr) * Rdst + r0 + ch * 8]) =
                        make_uint4(pk[0], pk[1], pk[2], pk[3]);
                }
                __syncthreads();
            }
            __threadfence();
            __syncthreads();
            if (tid == 0) atomicAdd(kind == 0 ? &g_wiT[e] : &g_woT[e], 1);
            continue;
        }

        // =========== GEMM items ===========
        const bool g1 = (kind == 2);
        const int mblk = g1 ? (sub >> 5) : (sub >> 3);
        const int nblk = g1 ? (sub & 31) : (sub & 7);

        const int row0 = g_off[e];
        const int ne   = g_off[e + 1] - row0;
        const int m0   = mblk * BM;
        if (m0 >= ne) continue;                  // empty tile
        const int mrows = min(BM, ne - m0);
        const int n0 = nblk * BN;
        const int Kdim = g1 ? HDIM : IDIM;

        // gates
        if (tid == 0) {
            if (g1) {
                while (atomicAdd(&g_wiT[e], 0) < 64) __nanosleep(100);
            } else {
                while (atomicAdd(&g_strip[e * 16 + mblk], 0) < 32 ||
                       atomicAdd(&g_woT[e], 0) < 64) __nanosleep(100);
            }
        }
        __syncthreads();

        if (tid < BM) {
            int r = min(tid, mrows - 1);
            sRow[tid] = g1 ? g_perm[row0 + m0 + r] : (row0 + m0 + r);
        }
        __syncthreads();

        const __nv_bfloat16* Abase = g1 ? g_lnb : g_hb;
        const __nv_bfloat16* Bbase = (g1 ? g_wib : g_wob)
                                   + (size_t)e * (size_t)IDIM * HDIM
                                   + (size_t)n0 * Kdim;

        float acc[4][4][4] = {};

        auto load_stage = [&](int kt, int buf) {
            const int k0 = kt * BK;
            #pragma unroll
            for (int h = 0; h < 2; h++) {
                int r = lr + h * 64;
                const __nv_bfloat16* src = Abase + (size_t)sRow[r] * Kdim + k0 + lkg * 8;
                uint32_t dst = smem_u32(&As[buf][r * LDK + lkg * 8]);
                asm volatile("cp.async.cg.shared.global [%0], [%1], 16;\n" :: "r"(dst), "l"(src));
            }
            #pragma unroll
            for (int h = 0; h < 2; h++) {
                int r = lr + h * 64;
                const __nv_bfloat16* src = Bbase + (size_t)r * Kdim + k0 + lkg * 8;
                uint32_t dst = smem_u32(&Bs[buf][r * LDK + lkg * 8]);
                asm volatile("cp.async.cg.shared.global [%0], [%1], 16;\n" :: "r"(dst), "l"(src));
            }
        };

        const int KT = Kdim / BK;
        load_stage(0, 0);
        asm volatile("cp.async.commit_group;\n");
        load_stage(1, 1);
        asm volatile("cp.async.commit_group;\n");

        int buf = 0;
        for (int kt = 0; kt < KT; kt++) {
            asm volatile("cp.async.wait_group 1;\n");
            __syncthreads();
            if (kt + 2 < KT) {
                load_stage(kt + 2, (buf + 2) % STAGES);
                asm volatile("cp.async.commit_group;\n");
            } else {
                asm volatile("cp.async.commit_group;\n");
            }

            #pragma unroll
            for (int ks = 0; ks < BK; ks += 16) {
                uint32_t a[4][4];
                #pragma unroll
                for (int mi = 0; mi < 4; mi++) {
                    const int amat = lane >> 3;
                    const int arow = wm + mi * 16 + (lane & 7) + (amat & 1) * 8;
                    const int acol = ks + (amat >> 1) * 8;
                    uint32_t addr = smem_u32(&As[buf][arow * LDK + acol]);
                    asm volatile("ldmatrix.sync.aligned.m8n8.x4.shared.b16 {%0,%1,%2,%3}, [%4];\n"
                        : "=r"(a[mi][0]), "=r"(a[mi][1]), "=r"(a[mi][2]), "=r"(a[mi][3]) : "r"(addr));
                }
                uint32_t b[4][2];
                #pragma unroll
                for (int p = 0; p < 2; p++) {
                    const int brow = wn + p * 16 + ((lane >> 4) << 3) + (lane & 7);
                    const int bcol = ks + (((lane >> 3) & 1) << 3);
                    uint32_t addr = smem_u32(&Bs[buf][brow * LDK + bcol]);
                    asm volatile("ldmatrix.sync.aligned.m8n8.x4.shared.b16 {%0,%1,%2,%3}, [%4];\n"
                        : "=r"(b[2*p][0]), "=r"(b[2*p][1]), "=r"(b[2*p+1][0]), "=r"(b[2*p+1][1]) : "r"(addr));
                }
                #pragma unroll
                for (int mi = 0; mi < 4; mi++)
                    #pragma unroll
                    for (int ni = 0; ni < 4; ni++)
                        asm volatile("mma.sync.aligned.m16n8k16.row.col.f32.bf16.bf16.f32 "
                            "{%0,%1,%2,%3},{%4,%5,%6,%7},{%8,%9},{%0,%1,%2,%3};\n"
                            : "+f"(acc[mi][ni][0]), "+f"(acc[mi][ni][1]),
                              "+f"(acc[mi][ni][2]), "+f"(acc[mi][ni][3])
                            : "r"(a[mi][0]), "r"(a[mi][1]), "r"(a[mi][2]), "r"(a[mi][3]),
                              "r"(b[ni][0]), "r"(b[ni][1]));
            }
            __syncthreads();
            buf = (buf + 1) % STAGES;
        }

        // ---------------- epilogue ----------------
        const int tg = lane & 3;
        const int gr = lane >> 2;
        if (g1) {
            #pragma unroll
            for (int mi = 0; mi < 4; mi++) {
                #pragma unroll
                for (int half = 0; half < 2; half++) {
                    const int m = wm + mi * 16 + gr + half * 8;
                    if (m < mrows) {
                        const size_t base = (size_t)(row0 + m0 + m) * IDIM + n0 + wn;
                        #pragma unroll
                        for (int ni = 0; ni < 4; ni++) {
                            float x0 = acc[mi][ni][half * 2 + 0];
                            float x1 = acc[mi][ni][half * 2 + 1];
                            float v0 = 0.5f * x0 * (1.0f + erff(x0 * 0.70710678118654752f));
                            float v1 = 0.5f * x1 * (1.0f + erff(x1 * 0.70710678118654752f));
                            __nv_bfloat162 pk = __floats2bfloat162_rn(v0, v1);
                            *reinterpret_cast<__nv_bfloat162*>(&g_hb[base + ni * 8 + tg * 2]) = pk;
                        }
                    }
                }
            }
            __threadfence();
            __syncthreads();
            if (tid == 0) atomicAdd(&g_strip[e * 16 + mblk], 1);
        } else {
            #pragma unroll
            for (int mi = 0; mi < 4; mi++) {
                #pragma unroll
                for (int half = 0; half < 2; half++) {
                    const int m = wm + mi * 16 + gr + half * 8;
                    if (m < mrows) {
                        const int tok = g_perm[row0 + m0 + m];
                        const float w = g_w[tok];
                        const size_t base = (size_t)tok * HDIM + n0 + wn;
                        #pragma unroll
                        for (int ni = 0; ni < 4; ni++) {
                            const int col = ni * 8 + tg * 2;
                            float2 r = *reinterpret_cast<const float2*>(&inp[base + col]);
                            float2 o;
                            o.x = r.x + w * acc[mi][ni][half * 2 + 0];
                            o.y = r.y + w * acc[mi][ni][half * 2 + 1];
                            *reinterpret_cast<float2*>(&out[base + col]) = o;
                        }
                    }
                }
            }
        }
    }
}

// =====================================================================
extern "C" void kernel_launch(void* const* d_in, const int* in_sizes, int n_in,
                              void* d_out, int out_size)
{
    const float* inputs = (const float*)d_in[0];   // [4,2048,1024]
    const float* gw     = (const float*)d_in[1];   // [8,1024]
    const float* gamma  = (const float*)d_in[2];   // [1024]
    const float* beta   = (const float*)d_in[3];   // [1024]
    const float* wi     = (const float*)d_in[4];   // [8,1024,4096]
    const float* wo     = (const float*)d_in[5];   // [8,4096,1024]
    float* out = (float*)d_out;

    ln_gate_kernel<<<S_TOK, 256>>>(
        (const float4*)inputs, (const float4*)gw,
        (const float4*)gamma, (const float4*)beta, (float4*)out);

    scan_kernel<<<1, 1024>>>();

    moe_fused<<<296, 256>>>(inputs, out, wi, wo);
}

// round 17
// speedup vs baseline: 1.0319x; 1.0319x over previous
#include <cuda_runtime.h>
#include <cuda_bf16.h>
#include <math.h>
#include <stdint.h>

// ---------------- problem dims ----------------
#define S_TOK   8192
#define HDIM    1024
#define EXP     8
#define IDIM    4096
#define CAP     2048

// ---------------- scratch (device globals) ----------------
__device__ __nv_bfloat16 g_lnb[(size_t)S_TOK * HDIM];        // 16 MB LN'ed tokens (bf16)
__device__ __nv_bfloat16 g_hb [(size_t)S_TOK * IDIM];        // 64 MB GEMM1 output (bf16)
__device__ __nv_bfloat16 g_wib[(size_t)EXP * IDIM * HDIM];   // 64 MB wi transposed: [e][n=IDIM][k=HDIM]
__device__ __nv_bfloat16 g_wob[(size_t)EXP * HDIM * IDIM];   // 64 MB wo transposed: [e][n=HDIM][k=IDIM]
__device__ int   g_top1[S_TOK];
__device__ float g_w[S_TOK];
__device__ int   g_perm[S_TOK];
__device__ int   g_off[EXP + 1];
__device__ int   g_work;                 // global work-queue cursor
__device__ int   g_strip[EXP * 16];      // per (expert, m-block) GEMM1 completion

__device__ __forceinline__ uint32_t smem_u32(const void* p) {
    return (uint32_t)__cvta_generic_to_shared(p);
}

// =====================================================================
// PREP kernel: LN+gating (blocks 0..8191), wi transpose (8192..16383),
// wo transpose (16384..24575). Bodies identical to proven versions;
// merged so transpose DRAM traffic hides under LN latency.
// =====================================================================
__global__ void __launch_bounds__(256) prep_kernel(
    const float4* __restrict__ in4,
    const float4* __restrict__ gw4,
    const float4* __restrict__ gamma4,
    const float4* __restrict__ beta4,
    float4* __restrict__ out4,
    const float* __restrict__ wi,
    const float* __restrict__ wo)
{
    __shared__ __align__(16) float tile[64][65];   // transpose staging (LN uses slivers)
    const int bid = blockIdx.x;
    const int tid = threadIdx.x;

    if (bid < S_TOK) {
        // ================= LN + gating (proven body) =================
        const int s = bid;
        const int lane = tid & 31, wid = tid >> 5;

        float4 x = in4[(size_t)s * 256 + tid];

        float lsum = x.x + x.y + x.z + x.w;
        float lsq  = x.x * x.x + x.y * x.y + x.z * x.z + x.w * x.w;
        #pragma unroll
        for (int off = 16; off > 0; off >>= 1) {
            lsum += __shfl_down_sync(0xffffffffu, lsum, off);
            lsq  += __shfl_down_sync(0xffffffffu, lsq,  off);
        }
        float* s_a = &tile[0][0];        // 8 floats
        float* s_b = &tile[0][8];        // 8 floats
        float* s_ms = &tile[0][16];      // mean, rstd
        float* s_l = &tile[1][0];        // 8x8
        if (lane == 0) { s_a[wid] = lsum; s_b[wid] = lsq; }
        __syncthreads();
        if (tid == 0) {
            float a = 0.f, b = 0.f;
            #pragma unroll
            for (int w = 0; w < 8; w++) { a += s_a[w]; b += s_b[w]; }
            float mean = a * (1.0f / HDIM);
            float var  = b * (1.0f / HDIM) - mean * mean;
            s_ms[0] = mean;
            s_ms[1] = rsqrtf(var + 1e-5f);
        }
        __syncthreads();
        const float mean = s_ms[0], rstd = s_ms[1];

        float4 g = gamma4[tid], bb = beta4[tid];
        float4 nrm;
        nrm.x = (x.x - mean) * rstd * g.x + bb.x;
        nrm.y = (x.y - mean) * rstd * g.y + bb.y;
        nrm.z = (x.z - mean) * rstd * g.z + bb.z;
        nrm.w = (x.w - mean) * rstd * g.w + bb.w;

        __nv_bfloat162 p0 = __floats2bfloat162_rn(nrm.x, nrm.y);
        __nv_bfloat162 p1 = __floats2bfloat162_rn(nrm.z, nrm.w);
        uint32_t* lnb32 = reinterpret_cast<uint32_t*>(g_lnb);
        lnb32[(size_t)s * 512 + tid * 2 + 0] = *reinterpret_cast<uint32_t*>(&p0);
        lnb32[(size_t)s * 512 + tid * 2 + 1] = *reinterpret_cast<uint32_t*>(&p1);

        out4[(size_t)s * 256 + tid] = x;   // residual pre-fill (covers dropped tokens)

        float p[EXP];
        #pragma unroll
        for (int e = 0; e < EXP; e++) {
            float4 w = gw4[(size_t)e * 256 + tid];
            p[e] = nrm.x * w.x + nrm.y * w.y + nrm.z * w.z + nrm.w * w.w;
        }
        #pragma unroll
        for (int e = 0; e < EXP; e++) {
            #pragma unroll
            for (int off = 16; off > 0; off >>= 1)
                p[e] += __shfl_down_sync(0xffffffffu, p[e], off);
        }
        if (lane == 0) {
            #pragma unroll
            for (int e = 0; e < EXP; e++) s_l[e * 8 + wid] = p[e];
        }
        __syncthreads();
        if (tid == 0) {
            float logit[EXP];
            #pragma unroll
            for (int e = 0; e < EXP; e++) {
                float v = 0.f;
                #pragma unroll
                for (int w = 0; w < 8; w++) v += s_l[e * 8 + w];
                logit[e] = v;
            }
            int best = 0; float bv = logit[0];
            #pragma unroll
            for (int e = 1; e < EXP; e++) if (logit[e] > bv) { bv = logit[e]; best = e; }
            float den = 0.f;
            #pragma unroll
            for (int e = 0; e < EXP; e++) den += expf(logit[e] - bv);
            g_top1[s] = best;
            g_w[s]    = 1.0f / den;
        }
    } else {
        // ================= weight transpose tile (proven body) =================
        const bool isWi = bid < 2 * S_TOK;
        const int id = bid - (isWi ? S_TOK : 2 * S_TOK);    // 0..8191
        const int e  = id >> 10;
        const int t  = id & 1023;
        int r0, c0, Csrc, Rdst;
        const float* src;
        __nv_bfloat16* dst;
        if (isWi) {     // wi [1024][4096] -> wib [4096][1024] ; 16 rblk x 64 cblk
            src = wi + (size_t)e * HDIM * IDIM;
            dst = g_wib + (size_t)e * (size_t)IDIM * HDIM;
            Csrc = IDIM; Rdst = HDIM;
            r0 = (t >> 6) * 64; c0 = (t & 63) * 64;
        } else {        // wo [4096][1024] -> wob [1024][4096] ; 64 rblk x 16 cblk
            src = wo + (size_t)e * IDIM * HDIM;
            dst = g_wob + (size_t)e * (size_t)HDIM * IDIM;
            Csrc = HDIM; Rdst = IDIM;
            r0 = (t >> 4) * 64; c0 = (t & 15) * 64;
        }

        {
            const int r  = tid >> 2;
            const int cg = (tid & 3) * 4;
            const float* srow = src + (size_t)(r0 + r) * Csrc + c0;
            #pragma unroll
            for (int i = 0; i < 4; i++) {
                float4 v = *reinterpret_cast<const float4*>(srow + (cg + i) * 4);
                tile[r][(cg + i) * 4 + 0] = v.x;
                tile[r][(cg + i) * 4 + 1] = v.y;
                tile[r][(cg + i) * 4 + 2] = v.z;
                tile[r][(cg + i) * 4 + 3] = v.w;
            }
        }
        __syncthreads();
        #pragma unroll
        for (int p = 0; p < 2; p++) {
            const int dr = p * 32 + (tid >> 3);
            const int ch = tid & 7;
            uint32_t pk[4];
            #pragma unroll
            for (int j = 0; j < 4; j++) {
                __nv_bfloat162 b2 = __floats2bfloat162_rn(tile[ch * 8 + 2 * j][dr],
                                                          tile[ch * 8 + 2 * j + 1][dr]);
                pk[j] = *reinterpret_cast<uint32_t*>(&b2);
            }
            *reinterpret_cast<uint4*>(&dst[(size_t)(c0 + dr) * Rdst + r0 + ch * 8]) =
                make_uint4(pk[0], pk[1], pk[2], pk[3]);
        }
    }
}

// =====================================================================
// K2: exact token-order exclusive cumsum per expert + capacity drop.
// Also resets work-queue / strip counters for the fused GEMM.
// =====================================================================
__device__ __forceinline__ uint4 u4add(uint4 a, uint4 b) {
    return make_uint4(a.x + b.x, a.y + b.y, a.z + b.z, a.w + b.w);
}

__global__ void __launch_bounds__(1024) scan_kernel()
{
    __shared__ uint4 s_wt[32];
    __shared__ int   s_koff[EXP + 1];

    const int tid = threadIdx.x;
    const int lane = tid & 31, wid = tid >> 5;

    // reset fused-GEMM bookkeeping (every launch; graph replays)
    if (tid < EXP * 16) g_strip[tid] = 0;
    if (tid == EXP * 16) g_work = 0;

    int t[8];
    uint4 cnt = make_uint4(0, 0, 0, 0);
    uint32_t* cw = reinterpret_cast<uint32_t*>(&cnt);
    #pragma unroll
    for (int j = 0; j < 8; j++) {
        t[j] = g_top1[tid * 8 + j];
        cw[t[j] >> 1] += 1u << ((t[j] & 1) * 16);
    }

    uint4 incl = cnt;
    uint32_t* iw = reinterpret_cast<uint32_t*>(&incl);
    #pragma unroll
    for (int off = 1; off < 32; off <<= 1) {
        uint4 up;
        uint32_t* uw = reinterpret_cast<uint32_t*>(&up);
        #pragma unroll
        for (int c = 0; c < 4; c++) uw[c] = __shfl_up_sync(0xffffffffu, iw[c], off);
        if (lane >= off) incl = u4add(incl, up);
    }
    if (lane == 31) s_wt[wid] = incl;
    __syncthreads();

    if (wid == 0) {
        uint4 v = s_wt[lane];
        uint32_t* vw = reinterpret_cast<uint32_t*>(&v);
        #pragma unroll
        for (int off = 1; off < 32; off <<= 1) {
            uint4 up;
            uint32_t* uw = reinterpret_cast<uint32_t*>(&up);
            #pragma unroll
            for (int c = 0; c < 4; c++) uw[c] = __shfl_up_sync(0xffffffffu, vw[c], off);
            if (lane >= off) v = u4add(v, up);
        }
        s_wt[lane] = v;
        if (lane == 31) {
            int o = 0;
            #pragma unroll
            for (int e = 0; e < EXP; e++) {
                int tot = (vw[e >> 1] >> ((e & 1) * 16)) & 0xffff;
                s_koff[e] = o;
                o += min(tot, CAP);
            }
            s_koff[EXP] = o;
            #pragma unroll
            for (int i = 0; i <= EXP; i++) g_off[i] = s_koff[i];
        }
    }
    __syncthreads();

    uint4 base = (wid > 0) ? s_wt[wid - 1] : make_uint4(0, 0, 0, 0);
    int excl[EXP];
    uint32_t* bw = reinterpret_cast<uint32_t*>(&base);
    #pragma unroll
    for (int e = 0; e < EXP; e++) {
        int sh = (e & 1) * 16;
        excl[e] = (int)(((bw[e >> 1] >> sh) & 0xffff)
                      + ((iw[e >> 1] >> sh) & 0xffff)
                      - ((cw[e >> 1] >> sh) & 0xffff));
    }
    #pragma unroll
    for (int j = 0; j < 8; j++) {
        int e = t[j];
        int r = excl[e]++;
        int s = tid * 8 + j;
        if (r < CAP) g_perm[s_koff[e] + r] = s;
        else         g_w[s] = 0.0f;
    }
}

// =====================================================================
// Fused persistent tensor-core GEMM (proven R15 version, 602us)
//   ids [0, 4096)      : GEMM1 tiles (e, mblk 0..15, nblk 0..31)
//   ids [4096, 5120)   : GEMM2 tiles (e, mblk 0..15, nblk 0..7), gated on
//                        per-strip GEMM1 completion counters.
// =====================================================================
#define BM 128
#define BN 128
#define BK 32
#define LDK 40
#define STAGES 3
#define N_ITEMS1 (EXP * 16 * 32)           // 4096
#define N_ITEMS  (N_ITEMS1 + EXP * 16 * 8) // 5120

__global__ void __launch_bounds__(256, 2) moe_fused(
    const float* __restrict__ inp, float* __restrict__ out)
{
    __shared__ __nv_bfloat16 As[STAGES][BM * LDK];
    __shared__ __nv_bfloat16 Bs[STAGES][BN * LDK];
    __shared__ int sRow[BM];
    __shared__ int s_item;

    const int tid = threadIdx.x;
    const int warp = tid >> 5, lane = tid & 31;
    const int wm = (warp >> 2) * 64;
    const int wn = (warp & 3) * 32;
    const int lr = tid >> 2;
    const int lkg = tid & 3;

    for (;;) {
        __syncthreads();                         // protect s_item + smem reuse
        if (tid == 0) s_item = atomicAdd(&g_work, 1);
        __syncthreads();
        const int id = s_item;
        if (id >= N_ITEMS) break;

        // ---- decode work item ----
        bool g1; int e, mblk, nblk;
        if (id < N_ITEMS1) {
            g1 = true;
            e = id >> 9;
            mblk = (id & 511) >> 5;
            nblk = id & 31;
        } else {
            g1 = false;
            const int id2 = id - N_ITEMS1;
            e = id2 >> 7;
            mblk = (id2 & 127) >> 3;
            nblk = id2 & 7;
        }

        const int row0 = g_off[e];
        const int ne   = g_off[e + 1] - row0;
        const int m0   = mblk * BM;
        if (m0 >= ne) continue;                  // empty tile (uniform)
        const int mrows = min(BM, ne - m0);
        const int n0 = nblk * BN;

        const int Kdim = g1 ? HDIM : IDIM;

        // ---- GEMM2: wait for this strip's GEMM1 tiles ----
        if (!g1) {
            if (tid == 0) {
                while (atomicAdd(&g_strip[e * 16 + mblk], 0) < 32) __nanosleep(100);
            }
            __syncthreads();
        }

        if (tid < BM) {
            int r = min(tid, mrows - 1);
            sRow[tid] = g1 ? g_perm[row0 + m0 + r] : (row0 + m0 + r);
        }
        __syncthreads();

        const __nv_bfloat16* Abase = g1 ? g_lnb : g_hb;
        const __nv_bfloat16* Bbase = (g1 ? g_wib : g_wob)
                                   + (size_t)e * (size_t)IDIM * HDIM
                                   + (size_t)n0 * Kdim;

        float acc[4][4][4] = {};

        auto load_stage = [&](int kt, int buf) {
            const int k0 = kt * BK;
            #pragma unroll
            for (int h = 0; h < 2; h++) {
                int r = lr + h * 64;
                const __nv_bfloat16* src = Abase + (size_t)sRow[r] * Kdim + k0 + lkg * 8;
                uint32_t dst = smem_u32(&As[buf][r * LDK + lkg * 8]);
                asm volatile("cp.async.cg.shared.global [%0], [%1], 16;\n" :: "r"(dst), "l"(src));
            }
            #pragma unroll
            for (int h = 0; h < 2; h++) {
                int r = lr + h * 64;
                const __nv_bfloat16* src = Bbase + (size_t)r * Kdim + k0 + lkg * 8;
                uint32_t dst = smem_u32(&Bs[buf][r * LDK + lkg * 8]);
                asm volatile("cp.async.cg.shared.global [%0], [%1], 16;\n" :: "r"(dst), "l"(src));
            }
        };

        const int KT = Kdim / BK;
        load_stage(0, 0);
        asm volatile("cp.async.commit_group;\n");
        load_stage(1, 1);
        asm volatile("cp.async.commit_group;\n");

        int buf = 0;
        for (int kt = 0; kt < KT; kt++) {
            asm volatile("cp.async.wait_group 1;\n");
            __syncthreads();
            if (kt + 2 < KT) {
                load_stage(kt + 2, (buf + 2) % STAGES);
                asm volatile("cp.async.commit_group;\n");
            } else {
                asm volatile("cp.async.commit_group;\n");
            }

            #pragma unroll
            for (int ks = 0; ks < BK; ks += 16) {
                uint32_t a[4][4];
                #pragma unroll
                for (int mi = 0; mi < 4; mi++) {
                    const int amat = lane >> 3;
                    const int arow = wm + mi * 16 + (lane & 7) + (amat & 1) * 8;
                    const int acol = ks + (amat >> 1) * 8;
                    uint32_t addr = smem_u32(&As[buf][arow * LDK + acol]);
                    asm volatile("ldmatrix.sync.aligned.m8n8.x4.shared.b16 {%0,%1,%2,%3}, [%4];\n"
                        : "=r"(a[mi][0]), "=r"(a[mi][1]), "=r"(a[mi][2]), "=r"(a[mi][3]) : "r"(addr));
                }
                uint32_t b[4][2];
                #pragma unroll
                for (int p = 0; p < 2; p++) {
                    const int brow = wn + p * 16 + ((lane >> 4) << 3) + (lane & 7);
                    const int bcol = ks + (((lane >> 3) & 1) << 3);
                    uint32_t addr = smem_u32(&Bs[buf][brow * LDK + bcol]);
                    asm volatile("ldmatrix.sync.aligned.m8n8.x4.shared.b16 {%0,%1,%2,%3}, [%4];\n"
                        : "=r"(b[2*p][0]), "=r"(b[2*p][1]), "=r"(b[2*p+1][0]), "=r"(b[2*p+1][1]) : "r"(addr));
                }
                #pragma unroll
                for (int mi = 0; mi < 4; mi++)
                    #pragma unroll
                    for (int ni = 0; ni < 4; ni++)
                        asm volatile("mma.sync.aligned.m16n8k16.row.col.f32.bf16.bf16.f32 "
                            "{%0,%1,%2,%3},{%4,%5,%6,%7},{%8,%9},{%0,%1,%2,%3};\n"
                            : "+f"(acc[mi][ni][0]), "+f"(acc[mi][ni][1]),
                              "+f"(acc[mi][ni][2]), "+f"(acc[mi][ni][3])
                            : "r"(a[mi][0]), "r"(a[mi][1]), "r"(a[mi][2]), "r"(a[mi][3]),
                              "r"(b[ni][0]), "r"(b[ni][1]));
            }
            __syncthreads();
            buf = (buf + 1) % STAGES;
        }

        // ---------------- epilogue ----------------
        const int tg = lane & 3;
        const int gr = lane >> 2;
        if (g1) {
            #pragma unroll
            for (int mi = 0; mi < 4; mi++) {
                #pragma unroll
                for (int half = 0; half < 2; half++) {
                    const int m = wm + mi * 16 + gr + half * 8;
                    if (m < mrows) {
                        const size_t base = (size_t)(row0 + m0 + m) * IDIM + n0 + wn;
                        #pragma unroll
                        for (int ni = 0; ni < 4; ni++) {
                            float x0 = acc[mi][ni][half * 2 + 0];
                            float x1 = acc[mi][ni][half * 2 + 1];
                            float v0 = 0.5f * x0 * (1.0f + erff(x0 * 0.70710678118654752f));
                            float v1 = 0.5f * x1 * (1.0f + erff(x1 * 0.70710678118654752f));
                            __nv_bfloat162 pk = __floats2bfloat162_rn(v0, v1);
                            *reinterpret_cast<__nv_bfloat162*>(&g_hb[base + ni * 8 + tg * 2]) = pk;
                        }
                    }
                }
            }
            // release: make h visible, then count this tile for the strip
            __threadfence();
            __syncthreads();
            if (tid == 0) atomicAdd(&g_strip[e * 16 + mblk], 1);
        } else {
            #pragma unroll
            for (int mi = 0; mi < 4; mi++) {
                #pragma unroll
                for (int half = 0; half < 2; half++) {
                    const int m = wm + mi * 16 + gr + half * 8;
                    if (m < mrows) {
                        const int tok = g_perm[row0 + m0 + m];
                        const float w = g_w[tok];
                        const size_t base = (size_t)tok * HDIM + n0 + wn;
                        #pragma unroll
                        for (int ni = 0; ni < 4; ni++) {
                            const int col = ni * 8 + tg * 2;
                            float2 r = *reinterpret_cast<const float2*>(&inp[base + col]);
                            float2 o;
                            o.x = r.x + w * acc[mi][ni][half * 2 + 0];
                            o.y = r.y + w * acc[mi][ni][half * 2 + 1];
                            *reinterpret_cast<float2*>(&out[base + col]) = o;
                        }
                    }
                }
            }
        }
    }
}

// =====================================================================
extern "C" void kernel_launch(void* const* d_in, const int* in_sizes, int n_in,
                              void* d_out, int out_size)
{
    const float* inputs = (const float*)d_in[0];   // [4,2048,1024]
    const float* gw     = (const float*)d_in[1];   // [8,1024]
    const float* gamma  = (const float*)d_in[2];   // [1024]
    const float* beta   = (const float*)d_in[3];   // [1024]
    const float* wi     = (const float*)d_in[4];   // [8,1024,4096]
    const float* wo     = (const float*)d_in[5];   // [8,4096,1024]
    float* out = (float*)d_out;

    prep_kernel<<<3 * S_TOK, 256>>>(
        (const float4*)inputs, (const float4*)gw,
        (const float4*)gamma, (const float4*)beta, (float4*)out, wi, wo);

    scan_kernel<<<1, 1024>>>();

    moe_fused<<<296, 256>>>(inputs, out);
}